// round 1
// baseline (speedup 1.0000x reference)
#include <cuda_runtime.h>
#include <math.h>

typedef unsigned long long ull;

#define DI __device__ __forceinline__

DI ull pk2(float x, float y){ ull r; asm("mov.b64 %0,{%1,%2};" : "=l"(r) : "f"(x), "f"(y)); return r; }
DI void upk2(ull v, float& x, float& y){ asm("mov.b64 {%0,%1},%2;" : "=f"(x), "=f"(y) : "l"(v)); }
DI ull ffma2(ull a, ull b, ull c){ ull d; asm("fma.rn.f32x2 %0,%1,%2,%3;" : "=l"(d) : "l"(a), "l"(b), "l"(c)); return d; }

static constexpr int B    = 32;
static constexpr int L    = 128;
static constexpr int H    = 1024;
static constexpr int EN   = 256;
static constexpr int ET   = 512;
static constexpr int EIN  = 768;     // EN + ET
static constexpr int G4   = 4096;    // 4*H
static constexpr int VOUT = 50003;
static constexpr int LOGN = VOUT + L;       // 50131
static constexpr int F3   = 3072;           // 3*H
static constexpr int NLOG = B * LOGN;       // logits elements
static constexpr int NCHUNK = 49;           // ceil(50003/1024)

// ---------------- scratch (static device memory; no allocations) ----------------
__device__ __align__(16) float g_xhT[(EIN + H) * B];   // [k][b]: emb-concat then h0
__device__ __align__(16) float g_featT[F3 * B];        // [k][b]: context | h_new | h_parent
__device__ __align__(16) float g_gates[G4 * B];        // [j][b]
__device__ __align__(16) float g_q[B * H];             // [b][j]
__device__ __align__(16) float g_scores[B * L];
__device__ float g_lse[B];
__device__ __align__(16) float g_context[B * H];
__device__ float g_sB[B];
__device__ float g_l1m[B];
__device__ __align__(16) float g_wgout[(VOUT + 32) * B]; // [v][b]
__device__ float g_pmax[NCHUNK * 32];
__device__ float g_psum[NCHUNK * 32];
__device__ float g_wlse[B];

// ---------------- K1: embeddings + transposed staging + score init ----------------
__global__ void k1_prep(const int* __restrict__ n_in, const int* __restrict__ t_in,
                        const float* __restrict__ h0, const float* __restrict__ h_parent,
                        const float* __restrict__ embN, const float* __restrict__ embT,
                        const float* __restrict__ v_b) {
    int b = blockIdx.x;
    int t = threadIdx.x;
    int n  = n_in[b];
    int tt = t_in[b];
    for (int k = t; k < EIN; k += blockDim.x) {
        float v = (k < EN) ? embN[n * EN + k] : embT[(size_t)tt * ET + (k - EN)];
        g_xhT[k * B + b] = v;
    }
    for (int k = t; k < H; k += blockDim.x) {
        g_xhT[(EIN + k) * B + b]     = h0[b * H + k];
        g_featT[(2 * H + k) * B + b] = h_parent[b * H + k];
    }
    if (t < L) g_scores[b * L + t] = v_b[0];
}

// ---------------- K2: LSTM gate GEMM (warp per output row) ----------------
__global__ void k2_gates(const float* __restrict__ W_ih, const float* __restrict__ W_hh,
                         const float* __restrict__ b_ih, const float* __restrict__ b_hh) {
    int wid = threadIdx.x >> 5, lane = threadIdx.x & 31;
    int j = blockIdx.x * 8 + wid;
    float acc = b_ih[j] + b_hh[j];
    const float* wi = W_ih + (size_t)j * EIN;
#pragma unroll 4
    for (int k = 0; k < EIN; k++) acc += wi[k] * g_xhT[k * B + lane];
    const float* wh = W_hh + (size_t)j * H;
    const float* xh = g_xhT + EIN * B;
#pragma unroll 4
    for (int k = 0; k < H; k++) acc += wh[k] * xh[k * B + lane];
    g_gates[j * B + lane] = acc;
}

// ---------------- K3: LSTM pointwise ----------------
__global__ void k3_lstm(const float* __restrict__ c0, float* __restrict__ d_out) {
    int idx = blockIdx.x * blockDim.x + threadIdx.x;   // 32768 total
    int b = idx & 31, j = idx >> 5;
    float gi = g_gates[j * B + b];
    float gf = g_gates[(H + j) * B + b];
    float gg = g_gates[(2 * H + j) * B + b];
    float go = g_gates[(3 * H + j) * B + b];
    float cp = c0[b * H + j];
    float si = 1.f / (1.f + expf(-gi));
    float sf = 1.f / (1.f + expf(-gf));
    float so = 1.f / (1.f + expf(-go));
    float cn = sf * cp + si * tanhf(gg);
    float hn = so * tanhf(cn);
    g_featT[(H + j) * B + b] = hn;                       // "out" feature section
    d_out[NLOG + b * H + j] = hn;                        // h_new output
    d_out[NLOG + B * H + b * H + j] = cn;                // c_new output
}

// ---------------- K4: q = Wh_w @ h_new + Wh_b ----------------
__global__ void k4_q(const float* __restrict__ Wh_w, const float* __restrict__ Wh_b) {
    int wid = threadIdx.x >> 5, lane = threadIdx.x & 31;
    int j = blockIdx.x * 8 + wid;
    float acc = Wh_b[j];
    const float* w  = Wh_w + (size_t)j * H;
    const float* hT = g_featT + H * B;
#pragma unroll 4
    for (int k = 0; k < H; k++) acc += w[k] * hT[k * B + lane];
    g_q[lane * H + j] = acc;
}

// ---------------- K5: attention GEMM (enc@Wm^T) with fused v*tanh(q+m) epilogue ----------------
// BM=128 (one batch's L rows), BN=64, BK=16, 256 threads, per-thread 8x4 via fma.f32x2
__global__ void __launch_bounds__(256) k5_score(const float* __restrict__ enc,
                                                const float* __restrict__ Wm_w,
                                                const float* __restrict__ Wm_b,
                                                const float* __restrict__ v_w) {
    __shared__ __align__(16) float AsD[16 * 256];  // duplicated A: [k][2*row]
    __shared__ __align__(16) float Bs[16 * 64];    // [k][j]
    __shared__ float red[128];
    int tid = threadIdx.x;
    int n0 = blockIdx.x * 64;
    int by = blockIdx.y;                 // batch (BM == L)
    int tm0 = (tid >> 4) * 8;
    int tn0 = (tid & 15) * 4;
    ull z = pk2(0.f, 0.f);
    ull acc[8][2];
#pragma unroll
    for (int i = 0; i < 8; i++) { acc[i][0] = z; acc[i][1] = z; }
    const float* A = enc + (size_t)by * L * H;

    for (int k0 = 0; k0 < H; k0 += 16) {
#pragma unroll
        for (int i = 0; i < 2; i++) {
            int idx = i * 256 + tid;
            int row = idx >> 2, c4 = idx & 3;
            float4 v = *(const float4*)&A[row * H + k0 + 4 * c4];
            float* p = &AsD[(4 * c4) * 256 + 2 * row];
            p[0] = v.x;   p[1] = v.x;
            p[256] = v.y; p[257] = v.y;
            p[512] = v.z; p[513] = v.z;
            p[768] = v.w; p[769] = v.w;
        }
        {
            int row = tid >> 2, c4 = tid & 3;
            float4 v = *(const float4*)&Wm_w[(size_t)(n0 + row) * H + k0 + 4 * c4];
            Bs[(4 * c4) * 64 + row] = v.x;
            Bs[(4 * c4 + 1) * 64 + row] = v.y;
            Bs[(4 * c4 + 2) * 64 + row] = v.z;
            Bs[(4 * c4 + 3) * 64 + row] = v.w;
        }
        __syncthreads();
#pragma unroll 8
        for (int k = 0; k < 16; k++) {
            ulonglong2 b2 = *(const ulonglong2*)&Bs[k * 64 + tn0];
#pragma unroll
            for (int i = 0; i < 8; i++) {
                ull a2 = *(const ull*)&AsD[k * 256 + 2 * (tm0 + i)];
                acc[i][0] = ffma2(a2, b2.x, acc[i][0]);
                acc[i][1] = ffma2(a2, b2.y, acc[i][1]);
            }
        }
        __syncthreads();
    }

    if (tid < 128) red[tid] = 0.f;
    __syncthreads();
    float4 vw = *(const float4*)&v_w[n0 + tn0];
    float4 mb = *(const float4*)&Wm_b[n0 + tn0];
    float4 qv = *(const float4*)&g_q[by * H + n0 + tn0];
#pragma unroll
    for (int i = 0; i < 8; i++) {
        float x0, x1, x2, x3;
        upk2(acc[i][0], x0, x1);
        upk2(acc[i][1], x2, x3);
        float p = vw.x * tanhf(x0 + mb.x + qv.x) + vw.y * tanhf(x1 + mb.y + qv.y)
                + vw.z * tanhf(x2 + mb.z + qv.z) + vw.w * tanhf(x3 + mb.w + qv.w);
        atomicAdd(&red[tm0 + i], p);
    }
    __syncthreads();
    if (tid < 128) atomicAdd(&g_scores[by * L + tid], red[tid]);
}

// ---------------- K7: softmax over L + context + featT(context) ----------------
__global__ void k7_ctx(const float* __restrict__ enc, const unsigned char* __restrict__ mask) {
    __shared__ float sc[128];
    __shared__ float redm[16];
    int b = blockIdx.x, t = threadIdx.x;
    if (t < 128) {
        float s = g_scores[b * L + t];
        if (mask[b * L + t]) s = -1e20f;
        sc[t] = s;
        g_scores[b * L + t] = s;   // masked scores for copy-logp path
    }
    __syncthreads();
    float m = (t < 128) ? sc[t] : -INFINITY;
#pragma unroll
    for (int o = 16; o > 0; o >>= 1) m = fmaxf(m, __shfl_xor_sync(~0u, m, o));
    if ((t & 31) == 0) redm[t >> 5] = m;
    __syncthreads();
    if (t == 0) {
        float mm = redm[0];
        for (int w = 1; w < 8; w++) mm = fmaxf(mm, redm[w]);
        redm[0] = mm;
    }
    __syncthreads();
    float mx = redm[0];
    float e = (t < 128) ? expf(sc[t] - mx) : 0.f;
    float s = e;
#pragma unroll
    for (int o = 16; o > 0; o >>= 1) s += __shfl_xor_sync(~0u, s, o);
    if ((t & 31) == 0) redm[8 + (t >> 5)] = s;
    __syncthreads();
    if (t == 0) {
        float ss = 0.f;
        for (int w = 0; w < 8; w++) ss += redm[8 + w];
        redm[8] = ss;
    }
    __syncthreads();
    float sum = redm[8];
    if (t < 128) sc[t] = e / sum;           // attention weights
    if (t == 0) g_lse[b] = mx + logf(sum);
    __syncthreads();
    const float* E = enc + (size_t)b * L * H;
#pragma unroll
    for (int jj = 0; jj < 4; jj++) {
        int j = t + jj * 256;
        float a = 0.f;
#pragma unroll 4
        for (int l = 0; l < 128; l++) a += sc[l] * E[l * H + j];
        g_context[b * H + j] = a;
        g_featT[j * B + b] = a;
    }
}

// ---------------- K8: pointer switch s_t + copy-logits output section ----------------
__global__ void k8_s(const float* __restrict__ ws_w, const float* __restrict__ ws_b,
                     float* __restrict__ d_out) {
    __shared__ float red[8];
    __shared__ float sh[2];
    int b = blockIdx.x, t = threadIdx.x;
    float a = 0.f;
    for (int j = t; j < H; j += 256) a += g_context[b * H + j] * ws_w[j];
    for (int j = t; j < H; j += 256) a += g_featT[(H + j) * B + b] * ws_w[H + j];
#pragma unroll
    for (int o = 16; o > 0; o >>= 1) a += __shfl_xor_sync(~0u, a, o);
    if ((t & 31) == 0) red[t >> 5] = a;
    __syncthreads();
    if (t == 0) {
        float zz = ws_b[0];
        for (int w = 0; w < 8; w++) zz += red[w];
        // s = log sigmoid(z); l1m = log(1 - sigmoid(z)) = log sigmoid(-z), clipped at log(1e-18)
        float s  = (zz >= 0.f) ? -log1pf(expf(-zz)) : zz - log1pf(expf(zz));
        float zm = -zz;
        float l1 = (zm >= 0.f) ? -log1pf(expf(-zm)) : zm - log1pf(expf(zm));
        l1 = fmaxf(l1, -41.446531673892822f);
        g_sB[b] = s;
        g_l1m[b] = l1;
        sh[0] = l1;
        sh[1] = g_lse[b];
    }
    __syncthreads();
    if (t < 128)
        d_out[(size_t)b * LOGN + VOUT + t] = sh[0] + g_scores[b * L + t] - sh[1];
}

// ---------------- K10: vocab GEMM: wgout[v][b] = wg_w[v,:] . feat[:, b] + wg_b[v] ----------------
// BM=128 rows, BK=32, 128 threads, per-thread 8 rows x 4 batches via fma.f32x2
__global__ void __launch_bounds__(128) k10_wg(const float* __restrict__ wg_w,
                                              const float* __restrict__ wg_b) {
    __shared__ __align__(16) float AsD[32 * 256];  // duplicated weights: [k][2*row]  (32KB)
    __shared__ __align__(16) float Bs[32 * 32];    // features [k][b]                 (4KB)
    int tid = threadIdx.x;
    int v0 = blockIdx.x * 128;
    int tm0 = (tid >> 3) * 8;
    int tb0 = (tid & 7) * 4;
    ull z = pk2(0.f, 0.f);
    ull acc[8][2];
#pragma unroll
    for (int i = 0; i < 8; i++) { acc[i][0] = z; acc[i][1] = z; }

    for (int k0 = 0; k0 < F3; k0 += 32) {
#pragma unroll
        for (int i = 0; i < 8; i++) {
            int idx = i * 128 + tid;
            int row = idx >> 3, c4 = idx & 7;
            int vr = v0 + row;
            if (vr > VOUT - 1) vr = VOUT - 1;
            float4 v = *(const float4*)&wg_w[(size_t)vr * F3 + k0 + 4 * c4];
            float* p = &AsD[(4 * c4) * 256 + 2 * row];
            p[0] = v.x;   p[1] = v.x;
            p[256] = v.y; p[257] = v.y;
            p[512] = v.z; p[513] = v.z;
            p[768] = v.w; p[769] = v.w;
        }
#pragma unroll
        for (int i = 0; i < 2; i++) {
            int idx = i * 128 + tid;
            ((float4*)Bs)[idx] = ((const float4*)(g_featT + k0 * B))[idx];
        }
        __syncthreads();
#pragma unroll 8
        for (int k = 0; k < 32; k++) {
            ulonglong2 b2 = *(const ulonglong2*)&Bs[k * 32 + tb0];
#pragma unroll
            for (int i = 0; i < 8; i++) {
                ull a2 = *(const ull*)&AsD[k * 256 + 2 * (tm0 + i)];
                acc[i][0] = ffma2(a2, b2.x, acc[i][0]);
                acc[i][1] = ffma2(a2, b2.y, acc[i][1]);
            }
        }
        __syncthreads();
    }
#pragma unroll
    for (int i = 0; i < 8; i++) {
        int v = v0 + tm0 + i;
        if (v < VOUT) {
            float bias = wg_b[v];
            float4 o;
            upk2(acc[i][0], o.x, o.y);
            upk2(acc[i][1], o.z, o.w);
            o.x += bias; o.y += bias; o.z += bias; o.w += bias;
            *(float4*)&g_wgout[(size_t)v * B + tb0] = o;
        }
    }
}

// ---------------- K11a/b: log-sum-exp over VOUT per batch ----------------
__global__ void k11a_lse() {
    __shared__ float pm[8][32];
    __shared__ float ps[8][32];
    int w = threadIdx.x >> 5, lane = threadIdx.x & 31;
    int base = blockIdx.x * 1024 + w * 128;
    float m = -INFINITY, s = 0.f;
    for (int i = 0; i < 128; i++) {
        int v = base + i;
        if (v < VOUT) {
            float x = g_wgout[(size_t)v * B + lane];
            if (x > m) { s = s * expf(m - x) + 1.f; m = x; }
            else       { s += expf(x - m); }
        }
    }
    pm[w][lane] = m; ps[w][lane] = s;
    __syncthreads();
    if (w == 0) {
        float M = pm[0][lane], S = ps[0][lane];
#pragma unroll
        for (int i = 1; i < 8; i++) {
            float m2 = pm[i][lane], s2 = ps[i][lane];
            float nm = fmaxf(M, m2);
            S = S * expf(M - nm) + s2 * expf(m2 - nm);
            M = nm;
        }
        g_pmax[blockIdx.x * 32 + lane] = M;
        g_psum[blockIdx.x * 32 + lane] = S;
    }
}

__global__ void k11b_lse() {
    int b = threadIdx.x;
    float M = g_pmax[b], S = g_psum[b];
    for (int i = 1; i < NCHUNK; i++) {
        float m2 = g_pmax[i * 32 + b], s2 = g_psum[i * 32 + b];
        float nm = fmaxf(M, m2);
        S = S * expf(M - nm) + s2 * expf(m2 - nm);
        M = nm;
    }
    g_wlse[b] = M + logf(S);
}

// ---------------- K12: transpose + final vocab logits write ----------------
__global__ void k12_out(float* __restrict__ d_out) {
    __shared__ float sm[32][33];
    int tx = threadIdx.x & 31, ty = threadIdx.x >> 5;  // 32 x 8
    int v0 = blockIdx.x * 32;
#pragma unroll
    for (int r = 0; r < 4; r++) {
        int row = r * 8 + ty;
        int v = v0 + row;
        if (v > VOUT - 1) v = VOUT - 1;
        sm[row][tx] = g_wgout[(size_t)v * B + tx];
    }
    __syncthreads();
#pragma unroll
    for (int r = 0; r < 4; r++) {
        int b = r * 8 + ty;
        int v = v0 + tx;
        if (v < VOUT)
            d_out[(size_t)b * LOGN + v] = g_sB[b] + sm[tx][b] - g_wlse[b];
    }
}

// ---------------- launch ----------------
extern "C" void kernel_launch(void* const* d_in, const int* in_sizes, int n_in,
                              void* d_out, int out_size) {
    const int*   n_input  = (const int*)d_in[0];
    const int*   t_input  = (const int*)d_in[1];
    const float* h0       = (const float*)d_in[2];
    const float* c0       = (const float*)d_in[3];
    const float* enc_out  = (const float*)d_in[4];
    const unsigned char* mask = (const unsigned char*)d_in[5];
    const float* h_parent = (const float*)d_in[6];
    const float* embN     = (const float*)d_in[7];
    const float* embT     = (const float*)d_in[8];
    const float* W_ih     = (const float*)d_in[9];
    const float* W_hh     = (const float*)d_in[10];
    const float* b_ih     = (const float*)d_in[11];
    const float* b_hh     = (const float*)d_in[12];
    const float* Wh_w     = (const float*)d_in[13];
    const float* Wh_b     = (const float*)d_in[14];
    const float* Wm_w     = (const float*)d_in[15];
    const float* Wm_b     = (const float*)d_in[16];
    const float* v_w      = (const float*)d_in[17];
    const float* v_b      = (const float*)d_in[18];
    const float* wg_w     = (const float*)d_in[19];
    const float* wg_b     = (const float*)d_in[20];
    const float* ws_w     = (const float*)d_in[21];
    const float* ws_b     = (const float*)d_in[22];
    float* out = (float*)d_out;

    k1_prep<<<B, 256>>>(n_input, t_input, h0, h_parent, embN, embT, v_b);
    k2_gates<<<G4 / 8, 256>>>(W_ih, W_hh, b_ih, b_hh);
    k3_lstm<<<(B * H) / 256, 256>>>(c0, out);
    k4_q<<<H / 8, 256>>>(Wh_w, Wh_b);
    k5_score<<<dim3(H / 64, B), 256>>>(enc_out, Wm_w, Wm_b, v_w);
    k7_ctx<<<B, 256>>>(enc_out, mask);
    k8_s<<<B, 256>>>(ws_w, ws_b, out);
    k10_wg<<<(VOUT + 127) / 128, 128>>>(wg_w, wg_b);
    k11a_lse<<<NCHUNK, 256>>>();
    k11b_lse<<<1, 32>>>();
    k12_out<<<(VOUT + 31) / 32, 256>>>(out);
}